// round 11
// baseline (speedup 1.0000x reference)
#include <cuda_runtime.h>
#include <cstdint>
#include <cstddef>

// Problem dims
#define BB   256      // batch
#define TT   512      // time
#define OBS  64
#define HH   256      // hidden
#define G3   768      // 3*H

// scan v8 config: 16 batch-groups x 8 unit-slices = 128 CTAs
#define NGB  16       // batch groups (16 batches each)
#define NSL  8        // unit slices (32 units each)
#define SNT  384      // scan threads (12 warps)
#define NC   96       // gate-cols per CTA (3 gates x 32 units)
#define WSLF (NC * HH)            // floats per W slice (24576)

// dynamic smem partition (bytes)
#define SM_W_BYTES    (64 * NC * 16)          // 98304: full W slice
#define SM_GSUM_BYTES (NSL * 16 * NC * 4)     // 49152
#define SM_XST_BYTES  (16 * NC * 4)           // 6144
#define SM_HOWN_BYTES (16 * 32 * 4)           // 2048
#define SCAN_DSMEM (SM_W_BYTES + SM_GSUM_BYTES + SM_XST_BYTES + SM_HOWN_BYTES) // 155648

typedef unsigned long long u64;

// ---------------- scratch (device globals: allocation-free) ----------------
__device__ float g_xg[(size_t)BB * TT * G3];              // 402 MB gate pre-activations
__device__ float g_y0[(size_t)BB * TT * HH];              // 134 MB layer-0 outputs
__device__ float g_wt[2][(size_t)NSL * WSLF];             // repacked W_hh slices per layer
__device__ float g_mail[(size_t)NGB * NSL * TT * 512];    // h slice mailboxes (134 MB)
__device__ int   g_flag[2][(size_t)NGB * TT * NSL];       // per-layer flags

// ---------------- helpers ----------------
__device__ __forceinline__ float2 unpk(u64 v) {
    float2 f; asm("mov.b64 {%0,%1}, %2;" : "=f"(f.x), "=f"(f.y) : "l"(v)); return f;
}
__device__ __forceinline__ u64 f2fma(u64 a, u64 b, u64 c) {
    u64 d; asm("fma.rn.f32x2 %0, %1, %2, %3;" : "=l"(d) : "l"(a), "l"(b), "l"(c)); return d;
}
__device__ __forceinline__ float sigmf(float x) {
    return 1.0f / (1.0f + __expf(-x));
}
__device__ __forceinline__ float tanh_fast(float x) {
    return 1.0f - __fdividef(2.0f, __expf(2.0f * x) + 1.0f);
}
__device__ __forceinline__ int ld_acq(const int* p) {
    int v; asm volatile("ld.global.acquire.gpu.b32 %0, [%1];" : "=r"(v) : "l"(p)); return v;
}
__device__ __forceinline__ uint32_t cvt_tf32(float x) {
    uint32_t r; asm("cvt.rna.tf32.f32 %0, %1;" : "=r"(r) : "f"(x)); return r;
}
__device__ __forceinline__ void mma_tf32(float* c, const uint32_t* a, const uint32_t* b) {
    asm volatile(
        "mma.sync.aligned.m16n8k8.row.col.f32.tf32.tf32.f32 "
        "{%0,%1,%2,%3}, {%4,%5,%6,%7}, {%8,%9}, {%0,%1,%2,%3};"
        : "+f"(c[0]), "+f"(c[1]), "+f"(c[2]), "+f"(c[3])
        : "r"(a[0]), "r"(a[1]), "r"(a[2]), "r"(a[3]), "r"(b[0]), "r"(b[1]));
}

// =====================================================================
// W_hh repack into 8 unit-slices, quad-major:
//   slice s owns units [32s, 32s+32); col c = gate*32 + (u&31)
// =====================================================================
__global__ void repack_whh(const float* __restrict__ W, float* __restrict__ out)
{
    const int gRow = blockIdx.x;      // 0..767
    const int k    = threadIdx.x;     // 0..255
    const float v  = W[(size_t)gRow * HH + k];
    const int gate = gRow >> 8;
    const int u    = gRow & 255;
    const int s    = u >> 5;
    const int c    = gate * 32 + (u & 31);
    out[(size_t)s * WSLF + (size_t)(k >> 2) * (NC * 4) + c * 4 + (k & 3)] = v;
}

__global__ void reset_flags(int* __restrict__ f)
{
    f[blockIdx.x * 1024 + threadIdx.x] = 0;
}

// =====================================================================
// Projection GEMM (tf32 tensor cores), unchanged from R9:
//   C[M][768] = A[M][K] @ W[768][K]^T + bias[768]
// =====================================================================
#define TBM 128
#define TBN 64
#define TBK 32

__global__ void __launch_bounds__(256) proj_tf32(
    const float* __restrict__ A, const float* __restrict__ Wt,
    const float* __restrict__ bias, float* __restrict__ C, int K)
{
    __shared__ float As[TBK][TBM + 4];
    __shared__ float Bs[TBK][TBN + 4];

    const int tid  = threadIdx.x;
    const int lane = tid & 31;
    const int warp = tid >> 5;
    const int wm   = warp & 3;
    const int wn   = warp >> 2;
    const int gid  = lane >> 2;
    const int tig  = lane & 3;
    const int m0   = blockIdx.y * TBM;
    const int n0   = blockIdx.x * TBN;

    float acc[2][4][4];
    #pragma unroll
    for (int mt = 0; mt < 2; ++mt)
        #pragma unroll
        for (int nt = 0; nt < 4; ++nt)
            #pragma unroll
            for (int r = 0; r < 4; ++r) acc[mt][nt][r] = 0.f;

    for (int k0 = 0; k0 < K; k0 += TBK) {
        #pragma unroll
        for (int i = 0; i < 4; ++i) {
            const int linear = tid + i * 256;
            const int row = linear >> 3;
            const int kq  = (linear & 7) << 2;
            float4 v = *(const float4*)&A[(size_t)(m0 + row) * K + k0 + kq];
            As[kq + 0][row] = v.x; As[kq + 1][row] = v.y;
            As[kq + 2][row] = v.z; As[kq + 3][row] = v.w;
        }
        #pragma unroll
        for (int i = 0; i < 2; ++i) {
            const int linear = tid + i * 256;
            const int row = linear >> 3;
            const int kq  = (linear & 7) << 2;
            float4 v = *(const float4*)&Wt[(size_t)(n0 + row) * K + k0 + kq];
            Bs[kq + 0][row] = v.x; Bs[kq + 1][row] = v.y;
            Bs[kq + 2][row] = v.z; Bs[kq + 3][row] = v.w;
        }
        __syncthreads();

        #pragma unroll
        for (int ks = 0; ks < TBK; ks += 8) {
            uint32_t af[2][4], bf[4][2];
            #pragma unroll
            for (int mt = 0; mt < 2; ++mt) {
                const int rm = wm * 32 + mt * 16 + gid;
                af[mt][0] = cvt_tf32(As[ks + tig][rm]);
                af[mt][1] = cvt_tf32(As[ks + tig][rm + 8]);
                af[mt][2] = cvt_tf32(As[ks + tig + 4][rm]);
                af[mt][3] = cvt_tf32(As[ks + tig + 4][rm + 8]);
            }
            #pragma unroll
            for (int nt = 0; nt < 4; ++nt) {
                const int nb = wn * 32 + nt * 8 + gid;
                bf[nt][0] = cvt_tf32(Bs[ks + tig][nb]);
                bf[nt][1] = cvt_tf32(Bs[ks + tig + 4][nb]);
            }
            #pragma unroll
            for (int mt = 0; mt < 2; ++mt)
                #pragma unroll
                for (int nt = 0; nt < 4; ++nt)
                    mma_tf32(acc[mt][nt], af[mt], bf[nt]);
        }
        __syncthreads();
    }

    #pragma unroll
    for (int mt = 0; mt < 2; ++mt) {
        const int rm = m0 + wm * 32 + mt * 16 + gid;
        #pragma unroll
        for (int nt = 0; nt < 4; ++nt) {
            const int nc = n0 + wn * 32 + nt * 8 + 2 * tig;
            const float b0 = bias[nc], b1 = bias[nc + 1];
            *(float2*)&C[(size_t)rm * G3 + nc] =
                make_float2(acc[mt][nt][0] + b0, acc[mt][nt][1] + b1);
            *(float2*)&C[(size_t)(rm + 8) * G3 + nc] =
                make_float2(acc[mt][nt][2] + b0, acc[mt][nt][3] + b1);
        }
    }
}

// =====================================================================
// Recurrent scan v8b — 8-way unit split, full-smem W, t-indexed mailboxes.
// All shared arrays carved from ONE dynamic smem allocation (155,648 B)
// to stay under the 48 KB static-smem limit.
// =====================================================================
template<bool WRITE_Y>
__global__ void __launch_bounds__(SNT, 1) scan_kernel(
    const float* __restrict__ xg, const float* __restrict__ wsl_base,
    const float* __restrict__ bhh, float* __restrict__ y, float* __restrict__ hout,
    float* __restrict__ mail, int* __restrict__ flag)
{
    extern __shared__ __align__(16) unsigned char smem_raw[];
    ulonglong2* Wsq  = (ulonglong2*)smem_raw;                         // [64][NC]
    float* gsum      = (float*)(smem_raw + SM_W_BYTES);               // [NSL][16][NC]
    float* xst       = (float*)(smem_raw + SM_W_BYTES + SM_GSUM_BYTES);          // [16][NC]
    float* hown      = (float*)(smem_raw + SM_W_BYTES + SM_GSUM_BYTES + SM_XST_BYTES); // [16][32]

    #define GSUM(ss, b, c) gsum[((ss) * 16 + (b)) * NC + (c)]
    #define XST(b, c)      xst[(b) * NC + (c)]
    #define HOWN(b, u)     hown[(b) * 32 + (u)]

    const int tid = threadIdx.x;
    const int bid = blockIdx.x;
    const int gb  = bid >> 3;                    // batch group
    const int so  = bid & 7;                     // own unit slice
    const int bb0 = gb * 16;

    const int s  = tid / 48;                     // source k-slice this thread consumes
    const int r  = tid % 48;
    const int cc = r % 24;                       // cols cc, cc+24, cc+48, cc+72
    const int bh = r / 24;                       // batches bh*8 .. bh*8+8

    const ulonglong2* __restrict__ wtu =
        (const ulonglong2*)(wsl_base + (size_t)so * WSLF);

    // load full W slice to smem (96 KB, coalesced)
    for (int i = tid; i < 64 * NC; i += SNT)
        Wsq[i] = wtu[i];
    for (int i = tid; i < 512; i += SNT)
        HOWN(i >> 5, i & 31) = 0.f;

    // combine constants (threads 0..255: unit ju, batches jb, jb+8)
    const int ju = tid & 31;
    const int jb = tid >> 5;
    float br = 0.f, bz = 0.f, bn = 0.f;
    if (tid < 256) {
        const int g = so * 32 + ju;
        br = bhh[g]; bz = bhh[HH + g]; bn = bhh[2 * HH + g];
    }

    const size_t STRB  = (size_t)TT * G3;
    const size_t STRBY = (size_t)TT * HH;
    // x loader: thread -> (batch xb, col-quad xc4)
    const int xb  = tid / 24;
    const int xc4 = tid % 24;
    const int xcol = ((xc4 * 4) >> 5) * 256 + so * 32 + ((xc4 * 4) & 31);
    const float* xldp = xg + (size_t)(bb0 + xb) * STRB + xcol;

    float* mail_out = mail + ((size_t)(gb * 8 + so) * TT) * 512;
    const float* mail_src = mail + ((size_t)(gb * 8 + s) * TT) * 512;
    int* flag_grp = flag + (size_t)gb * TT * NSL;

    __syncthreads();

    for (int t = 0; t < TT; ++t) {
        // x prefetch (issued before any wait)
        float4 xv = *(const float4*)(xldp + (size_t)t * G3);

        u64 acc[4][8];
        #pragma unroll
        for (int i = 0; i < 4; ++i)
            #pragma unroll
            for (int j = 0; j < 8; ++j) acc[i][j] = 0ULL;

        if (t > 0) {
            // wait for source slice h(t-1) (acquire load orders the mail reads)
            const int* fp = flag_grp + (size_t)(t - 1) * NSL + s;
            while (ld_acq(fp) == 0) { }
            const float* ms = mail_src + (size_t)(t - 1) * 512 + bh * 8 * 32;
            #pragma unroll 2
            for (int q = 0; q < 8; ++q) {
                const ulonglong2* wrow = Wsq + (s * 8 + q) * NC;
                ulonglong2 w0 = wrow[cc];
                ulonglong2 w1 = wrow[cc + 24];
                ulonglong2 w2 = wrow[cc + 48];
                ulonglong2 w3 = wrow[cc + 72];
                #pragma unroll
                for (int b = 0; b < 8; ++b) {
                    ulonglong2 h = *(const ulonglong2*)(ms + b * 32 + 4 * q);
                    acc[0][b] = f2fma(w0.x, h.x, acc[0][b]);
                    acc[0][b] = f2fma(w0.y, h.y, acc[0][b]);
                    acc[1][b] = f2fma(w1.x, h.x, acc[1][b]);
                    acc[1][b] = f2fma(w1.y, h.y, acc[1][b]);
                    acc[2][b] = f2fma(w2.x, h.x, acc[2][b]);
                    acc[2][b] = f2fma(w2.y, h.y, acc[2][b]);
                    acc[3][b] = f2fma(w3.x, h.x, acc[3][b]);
                    acc[3][b] = f2fma(w3.y, h.y, acc[3][b]);
                }
            }
        }

        // fold k-pair lanes, publish partials
        #pragma unroll
        for (int ci = 0; ci < 4; ++ci)
            #pragma unroll
            for (int b = 0; b < 8; ++b) {
                float2 f = unpk(acc[ci][b]);
                GSUM(s, bh * 8 + b, cc + 24 * ci) = f.x + f.y;
            }
        *(float4*)&XST(xb, xc4 * 4) = xv;
        __syncthreads();

        // combine: 256 threads x 2 (batch, unit) items — fully local
        if (tid < 256) {
            #pragma unroll
            for (int it = 0; it < 2; ++it) {
                const int b = jb + it * 8;
                float R = 0.f, Z = 0.f, Nv = 0.f;
                #pragma unroll
                for (int ss = 0; ss < NSL; ++ss) {
                    R  += GSUM(ss, b, ju);
                    Z  += GSUM(ss, b, 32 + ju);
                    Nv += GSUM(ss, b, 64 + ju);
                }
                const float rr = sigmf(R + XST(b, ju) + br);
                const float zz = sigmf(Z + XST(b, 32 + ju) + bz);
                const float nn = tanh_fast(XST(b, 64 + ju) + rr * (Nv + bn));
                const float h = (1.0f - zz) * nn + zz * HOWN(b, ju);
                HOWN(b, ju) = h;
                mail_out[(size_t)t * 512 + b * 32 + ju] = h;
                if (WRITE_Y)
                    y[(size_t)(bb0 + b) * STRBY + (size_t)t * HH + so * 32 + ju] = h;
            }
        }
        __syncthreads();

        // release own slice h(t)
        if (tid == 0) {
            __threadfence();
            atomicExch(flag_grp + (size_t)t * NSL + so, 1);
        }
    }

    if (!WRITE_Y && tid < 256) {
        hout[(size_t)(bb0 + jb)     * HH + so * 32 + ju] = HOWN(jb, ju);
        hout[(size_t)(bb0 + jb + 8) * HH + so * 32 + ju] = HOWN(jb + 8, ju);
    }

    #undef GSUM
    #undef XST
    #undef HOWN
}

// =====================================================================
// launch
// =====================================================================
extern "C" void kernel_launch(void* const* d_in, const int* in_sizes, int n_in,
                              void* d_out, int out_size)
{
    const float* obs   = (const float*)d_in[0];
    const float* w_ih0 = (const float*)d_in[1];
    const float* w_hh0 = (const float*)d_in[2];
    const float* b_ih0 = (const float*)d_in[3];
    const float* b_hh0 = (const float*)d_in[4];
    const float* w_ih1 = (const float*)d_in[5];
    const float* w_hh1 = (const float*)d_in[6];
    const float* b_ih1 = (const float*)d_in[7];
    const float* b_hh1 = (const float*)d_in[8];
    float* out = (float*)d_out;

    void* xg_p = nullptr;  cudaGetSymbolAddress(&xg_p, g_xg);
    void* y0_p = nullptr;  cudaGetSymbolAddress(&y0_p, g_y0);
    void* wt_p = nullptr;  cudaGetSymbolAddress(&wt_p, g_wt);
    void* ml_p = nullptr;  cudaGetSymbolAddress(&ml_p, g_mail);
    void* fl_p = nullptr;  cudaGetSymbolAddress(&fl_p, g_flag);
    float* xg   = (float*)xg_p;
    float* y0   = (float*)y0_p;
    float* mail = (float*)ml_p;
    float* wsl0 = (float*)wt_p;
    float* wsl1 = wsl0 + (size_t)NSL * WSLF;
    int*   flag0 = (int*)fl_p;
    int*   flag1 = flag0 + (size_t)NGB * TT * NSL;

    cudaFuncSetAttribute(scan_kernel<true>,  cudaFuncAttributeMaxDynamicSharedMemorySize, SCAN_DSMEM);
    cudaFuncSetAttribute(scan_kernel<false>, cudaFuncAttributeMaxDynamicSharedMemorySize, SCAN_DSMEM);

    const int M = BB * TT;                 // 131072
    dim3 pgrid(G3 / TBN, M / TBM);         // (12, 1024)

    // launches 1-4: resets + repacks (ncu -s 5 then captures scan0 at #6)
    reset_flags<<<64, 1024>>>(flag0);
    reset_flags<<<64, 1024>>>(flag1);
    repack_whh<<<G3, HH>>>(w_hh0, wsl0);
    repack_whh<<<G3, HH>>>(w_hh1, wsl1);

    // layer 0
    proj_tf32<<<pgrid, 256>>>(obs, w_ih0, b_ih0, xg, OBS);
    scan_kernel<true><<<NGB * NSL, SNT, SCAN_DSMEM>>>(xg, wsl0, b_hh0, y0, nullptr, mail, flag0);
    // layer 1
    proj_tf32<<<pgrid, 256>>>(y0, w_ih1, b_ih1, xg, HH);
    scan_kernel<false><<<NGB * NSL, SNT, SCAN_DSMEM>>>(xg, wsl1, b_hh1, nullptr, out, mail, flag1);
}